// round 8
// baseline (speedup 1.0000x reference)
#include <cuda_runtime.h>
#include <cuda_bf16.h>
#include <math.h>
#include <stdint.h>
#include <mma.h>

using namespace nvcuda;

#define N_NODES 20000
#define N_EDGES 640000
#define HID 256
#define NH (N_NODES * HID)
#define N_LAYERS 5
#define KTOT 512       // stored split K (hi | lo)
#define GKCH 32        // GEMM K elements per pipelined chunk
#define GNCH 24        // 3 segments x 8 chunks: (hi,hi) (lo,hi) (hi,lo)
#define GLDA 40        // gemm smem leading dim (bf16; 80B, 16B-multiple)
#define LDS_STAGE 68   // epilogue staging ld (floats; 272B, 16B-multiple)

// ---------------- scratch ----------------
__device__ float g_h[2][NH];
__device__ float g_q[NH], g_k[NH], g_v[NH], g_sk[NH];
__device__ __align__(256) __nv_bfloat16 g_hb[N_NODES * KTOT];            // A split [M, hi|lo]
__device__ __align__(256) __nv_bfloat16 g_Wb[4 * N_LAYERS * 256 * KTOT]; // B split [N, hi|lo]
__device__ float g_M[46 * HID];
__device__ float g_bias[HID];
__device__ float g_skbias[N_LAYERS * HID];
__device__ int g_deg[N_NODES];
__device__ int g_offs[N_NODES + 1];
__device__ int g_cursor[N_NODES];
__device__ int g_ssrc[N_EDGES];
__device__ int g_seid[N_EDGES];

__device__ __forceinline__ void split_store(float v, __nv_bfloat16* hi_p, __nv_bfloat16* lo_p) {
    __nv_bfloat16 h = __float2bfloat16(v);
    *hi_p = h;
    *lo_p = __float2bfloat16(v - __bfloat162float(h));
}
__device__ __forceinline__ float dot4(float4 a, float4 b) {
    return a.x * b.x + a.y * b.y + a.z * b.z + a.w * b.w;
}
__device__ __forceinline__ void split4(float4 v, uint2* hi, uint2* lo) {
    __nv_bfloat16 hx = __float2bfloat16(v.x), hy = __float2bfloat16(v.y);
    __nv_bfloat16 hz = __float2bfloat16(v.z), hw = __float2bfloat16(v.w);
    __nv_bfloat162 h01 = __nv_bfloat162(hx, hy), h23 = __nv_bfloat162(hz, hw);
    hi->x = *reinterpret_cast<uint32_t*>(&h01);
    hi->y = *reinterpret_cast<uint32_t*>(&h23);
    __nv_bfloat162 l01 = __nv_bfloat162(__float2bfloat16(v.x - __bfloat162float(hx)),
                                        __float2bfloat16(v.y - __bfloat162float(hy)));
    __nv_bfloat162 l23 = __nv_bfloat162(__float2bfloat16(v.z - __bfloat162float(hz)),
                                        __float2bfloat16(v.w - __bfloat162float(hw)));
    lo->x = *reinterpret_cast<uint32_t*>(&l01);
    lo->y = *reinterpret_cast<uint32_t*>(&l23);
}
__device__ __forceinline__ void cp16(void* dst_smem, const void* src) {
    uint32_t d = (uint32_t)__cvta_generic_to_shared(dst_smem);
    asm volatile("cp.async.cg.shared.global [%0], [%1], 16;" :: "r"(d), "l"(src));
}
#define CP_COMMIT() asm volatile("cp.async.commit_group;" ::: "memory")
#define CP_WAIT1() asm volatile("cp.async.wait_group 1;" ::: "memory")
#define CP_WAIT0() asm volatile("cp.async.wait_group 0;" ::: "memory")

// ---------------- weight conversion: W[K,N] fp32 -> Wb[N, 512] bf16 (hi|lo) ----------------
__global__ void wconv_kernel(const float* __restrict__ Wq, const float* __restrict__ Wk,
                             const float* __restrict__ Wv, const float* __restrict__ Wsk) {
    __shared__ float s[32][33];
    int z = blockIdx.z;
    int w = z / N_LAYERS, l = z % N_LAYERS;
    const float* src = (w == 0) ? Wq : (w == 1) ? Wk : (w == 2) ? Wv : Wsk;
    src += l * 65536;
    __nv_bfloat16* dst = g_Wb + (size_t)z * 256 * KTOT;
    int k0 = blockIdx.x * 32, n0 = blockIdx.y * 32;
    int tx = threadIdx.x & 31, ty = threadIdx.x >> 5;
#pragma unroll
    for (int it = 0; it < 4; it++) {
        int r = ty + it * 8;
        s[r][tx] = src[(k0 + r) * 256 + n0 + tx];
    }
    __syncthreads();
#pragma unroll
    for (int it = 0; it < 4; it++) {
        int r = ty + it * 8;
        float v = s[tx][r];
        split_store(v, dst + (size_t)(n0 + r) * KTOT + k0 + tx,
                    dst + (size_t)(n0 + r) * KTOT + 256 + k0 + tx);
    }
}

// ---------------- fused encoder weights + skip-bias fold ----------------
__global__ void fuse_kernel(const float* __restrict__ W_emb, const float* __restrict__ W_t,
                            const float* __restrict__ W_s, const float* __restrict__ W_f,
                            const float* __restrict__ b_emb, const float* __restrict__ b_t,
                            const float* __restrict__ b_s, const float* __restrict__ b_f,
                            const float* __restrict__ bskip, const float* __restrict__ be) {
    int c = threadIdx.x;
    int r = blockIdx.x;
    if (r < 36) {
        float a = 0.f;
        for (int k = 0; k < 256; k++) a += W_emb[r * 256 + k] * W_f[k * 256 + c];
        g_M[r * 256 + c] = a;
    } else if (r < 40) {
        int rr = r - 36;
        float a = 0.f;
        for (int k = 0; k < 256; k++) a += W_t[rr * 256 + k] * W_f[(256 + k) * 256 + c];
        g_M[r * 256 + c] = a;
    } else if (r < 46) {
        int rr = r - 40;
        float a = 0.f;
        for (int k = 0; k < 256; k++) a += W_s[rr * 256 + k] * W_f[(512 + k) * 256 + c];
        g_M[r * 256 + c] = a;
    } else if (r == 46) {
        float a = b_f[c];
        for (int k = 0; k < 256; k++) {
            a += b_emb[k] * W_f[k * 256 + c];
            a += b_t[k] * W_f[(256 + k) * 256 + c];
            a += b_s[k] * W_f[(512 + k) * 256 + c];
        }
        g_bias[c] = a;
    } else {
        int l = r - 47;
        g_skbias[l * 256 + c] = bskip[l * 256 + c] + be[l * 256 + c];
    }
}

// ---------------- encoder ----------------
__global__ void encoder_kernel(const float* __restrict__ x, const float* __restrict__ t,
                               const float* __restrict__ s, const float* __restrict__ ln_g,
                               const float* __restrict__ ln_b) {
    __shared__ float sM[46 * 256];
    __shared__ float sb[256];
    __shared__ float sin_v[46];
    __shared__ float red[16];
    int tid = threadIdx.x;
    for (int i = tid; i < 46 * 256; i += 256) sM[i] = g_M[i];
    sb[tid] = g_bias[tid];
    float lg = ln_g[tid], lb = ln_b[tid];
    __syncthreads();
    for (int node = blockIdx.x; node < N_NODES; node += gridDim.x) {
        if (tid < 36) sin_v[tid] = x[node * 36 + tid];
        else if (tid < 40) sin_v[tid] = t[node * 4 + (tid - 36)];
        else if (tid < 46) sin_v[tid] = s[node * 6 + (tid - 40)];
        __syncthreads();
        float acc = sb[tid];
#pragma unroll
        for (int r = 0; r < 46; r++) acc += sin_v[r] * sM[r * 256 + tid];
        float ssum = acc, ssq = acc * acc;
#pragma unroll
        for (int o = 16; o; o >>= 1) {
            ssum += __shfl_xor_sync(0xffffffffu, ssum, o);
            ssq += __shfl_xor_sync(0xffffffffu, ssq, o);
        }
        if ((tid & 31) == 0) { red[tid >> 5] = ssum; red[8 + (tid >> 5)] = ssq; }
        __syncthreads();
        if (tid < 32) {
            float a = (tid < 8) ? red[tid] : 0.f;
            float b = (tid < 8) ? red[8 + tid] : 0.f;
#pragma unroll
            for (int o = 4; o; o >>= 1) {
                a += __shfl_xor_sync(0xffffffffu, a, o);
                b += __shfl_xor_sync(0xffffffffu, b, o);
            }
            if (tid == 0) { red[0] = a; red[1] = b; }
        }
        __syncthreads();
        float mu = red[0] * (1.f / 256.f);
        float var = red[1] * (1.f / 256.f) - mu * mu;
        float val = fmaxf((acc - mu) * rsqrtf(var + 1e-5f) * lg + lb, 0.f);
        g_h[0][node * 256 + tid] = val;
        split_store(val, g_hb + (size_t)node * KTOT + tid, g_hb + (size_t)node * KTOT + 256 + tid);
        __syncthreads();
    }
}

// ---------------- CSR build ----------------
__global__ void zero_deg_kernel() {
    int i = blockIdx.x * blockDim.x + threadIdx.x;
    if (i < N_NODES) g_deg[i] = 0;
}
__global__ void hist_kernel(const int* __restrict__ ei) {
    int e = blockIdx.x * blockDim.x + threadIdx.x;
    if (e < N_EDGES) atomicAdd(&g_deg[ei[N_EDGES + e]], 1);
}
__global__ void scan_kernel() {
    __shared__ int sh[1024];
    __shared__ int carry;
    int tid = threadIdx.x;
    if (tid == 0) carry = 0;
    __syncthreads();
    for (int base = 0; base < N_NODES; base += 1024) {
        int i = base + tid;
        int v = (i < N_NODES) ? g_deg[i] : 0;
        sh[tid] = v;
        __syncthreads();
        for (int off = 1; off < 1024; off <<= 1) {
            int tadd = (tid >= off) ? sh[tid - off] : 0;
            __syncthreads();
            sh[tid] += tadd;
            __syncthreads();
        }
        int incl = sh[tid];
        if (i < N_NODES) g_offs[i] = carry + incl - v;
        __syncthreads();
        if (tid == 1023) carry += sh[1023];
        __syncthreads();
    }
    if (tid == 0) g_offs[N_NODES] = carry;
}
__global__ void cursor_kernel() {
    int i = blockIdx.x * blockDim.x + threadIdx.x;
    if (i < N_NODES) g_cursor[i] = g_offs[i];
}
__global__ void scatter_kernel(const int* __restrict__ ei) {
    int e = blockIdx.x * blockDim.x + threadIdx.x;
    if (e < N_EDGES) {
        int d = ei[N_EDGES + e];
        int pos = atomicAdd(&g_cursor[d], 1);
        g_ssrc[pos] = ei[e];
        g_seid[pos] = e;
    }
}

// ---------------- bf16 wmma GEMM, 128x128 tile, cp.async double-buffered ----------------
// 8 warps as 4x2; warp tile 32x64 (2x4 frags). K chunk 32, 24 chunks (3-term split).
__global__ void __launch_bounds__(256)
gemm_wb(int layer, const float* __restrict__ bq_, const float* __restrict__ bk_,
        const float* __restrict__ bv_) {
    // [buf][ A 128x40 | B 128x40 ] bf16 = 2 x 10240 elems; total 40960B
    __shared__ __align__(16) __nv_bfloat16 smem_all[2 * 2 * 128 * GLDA];
    __shared__ float sbias[128];

    int tid = threadIdx.x;
    int wid = tid >> 5, lane = tid & 31;
    int wr = wid >> 1, wc = wid & 1;
    int w = blockIdx.z;
    int row0 = blockIdx.x * 128;
    int colblk = blockIdx.y * 128;
    int col0 = colblk + wc * 64;

    const __nv_bfloat16* Bsrc = g_Wb + ((size_t)w * N_LAYERS + layer) * 256 * KTOT;
    float* C;
    const float* bias;
    if (w == 0) { C = g_q; bias = bq_ + layer * 256; }
    else if (w == 1) { C = g_k; bias = bk_ + layer * 256; }
    else if (w == 2) { C = g_v; bias = bv_ + layer * 256; }
    else { C = g_sk; bias = g_skbias + layer * 256; }

    if (tid < 128) sbias[tid] = bias[colblk + tid];

    // per-thread cp.async source row/col: 512 16B-lines per tile, 2 per thread
    // line l: row = l>>2, k8 = (l&3)*8
    int l0 = tid, l1 = tid + 256;
    int ar0 = l0 >> 2, ak0 = (l0 & 3) * 8;
    int ar1 = l1 >> 2, ak1 = (l1 & 3) * 8;
    int gr0 = row0 + ar0; if (gr0 >= N_NODES) gr0 = N_NODES - 1;  // clamp: garbage rows never stored
    int gr1 = row0 + ar1; if (gr1 >= N_NODES) gr1 = N_NODES - 1;

    wmma::fragment<wmma::accumulator, 16, 16, 16, float> acc[2][4];
#pragma unroll
    for (int m = 0; m < 2; m++)
#pragma unroll
        for (int n = 0; n < 4; n++) wmma::fill_fragment(acc[m][n], 0.f);

    // chunk c: seg = c>>3 selects term; cc = c&7 is K-position
    auto issue = [&](int c, int buf) {
        int seg = c >> 3, cc = c & 7;
        int aoff = (seg == 1) ? 256 : 0;
        int boff = (seg == 2) ? 256 : 0;
        __nv_bfloat16* As = smem_all + buf * 2 * 128 * GLDA;
        __nv_bfloat16* Bs = As + 128 * GLDA;
        cp16(As + ar0 * GLDA + ak0, g_hb + (size_t)gr0 * KTOT + aoff + cc * GKCH + ak0);
        cp16(As + ar1 * GLDA + ak1, g_hb + (size_t)gr1 * KTOT + aoff + cc * GKCH + ak1);
        cp16(Bs + ar0 * GLDA + ak0, Bsrc + (size_t)(colblk + ar0) * KTOT + boff + cc * GKCH + ak0);
        cp16(Bs + ar1 * GLDA + ak1, Bsrc + (size_t)(colblk + ar1) * KTOT + boff + cc * GKCH + ak1);
        CP_COMMIT();
    };

    issue(0, 0);
    for (int c = 0; c < GNCH; c++) {
        if (c + 1 < GNCH) { issue(c + 1, (c + 1) & 1); CP_WAIT1(); }
        else { CP_WAIT0(); }
        __syncthreads();
        __nv_bfloat16* As = smem_all + (c & 1) * 2 * 128 * GLDA;
        __nv_bfloat16* Bs = As + 128 * GLDA;
#pragma unroll
        for (int ks = 0; ks < 2; ks++) {
            wmma::fragment<wmma::matrix_a, 16, 16, 16, __nv_bfloat16, wmma::row_major> af[2];
            wmma::fragment<wmma::matrix_b, 16, 16, 16, __nv_bfloat16, wmma::col_major> bf[4];
#pragma unroll
            for (int m = 0; m < 2; m++)
                wmma::load_matrix_sync(af[m], As + (wr * 32 + m * 16) * GLDA + ks * 16, GLDA);
#pragma unroll
            for (int n = 0; n < 4; n++)
                wmma::load_matrix_sync(bf[n], Bs + (wc * 64 + n * 16) * GLDA + ks * 16, GLDA);
#pragma unroll
            for (int m = 0; m < 2; m++)
#pragma unroll
                for (int n = 0; n < 4; n++) wmma::mma_sync(acc[m][n], af[m], bf[n], acc[m][n]);
        }
        __syncthreads();
    }

    // epilogue: per-warp 16x64 staging patch (overlays smem_all), ldm 68 floats
    float* stage = reinterpret_cast<float*>(smem_all) + wid * 16 * LDS_STAGE;  // 34816B <= 40960B
#pragma unroll
    for (int m = 0; m < 2; m++) {
        __syncwarp();
#pragma unroll
        for (int n = 0; n < 4; n++)
            wmma::store_matrix_sync(stage + n * 16, acc[m][n], LDS_STAGE, wmma::mem_row_major);
        __syncwarp();
        int rbase = row0 + wr * 32 + m * 16;
#pragma unroll
        for (int i = lane; i < 16 * 64; i += 32) {
            int r = i >> 6, cc2 = i & 63;
            int gr = rbase + r;
            if (gr < N_NODES)
                C[(size_t)gr * 256 + col0 + cc2] = stage[r * LDS_STAGE + cc2] + sbias[wc * 64 + cc2];
        }
        __syncwarp();
    }
}

// ---------------- attention: float4 lanes + one-edge register prefetch ----------------
__global__ void attn_kernel(const float* __restrict__ We_l, const float* __restrict__ edge_attr,
                            int pin) {
    __shared__ float sWe[8 * 256];
    for (int i = threadIdx.x; i < 2048; i += blockDim.x) sWe[i] = We_l[i];
    __syncthreads();
    const float4* sWe4 = reinterpret_cast<const float4*>(sWe);
    int w = (blockIdx.x * blockDim.x + threadIdx.x) >> 5;
    int lane = threadIdx.x & 31;
    if (w >= N_NODES) return;
    float* hout = g_h[pin ^ 1];

    float4 q0 = *reinterpret_cast<const float4*>(g_q + (size_t)w * 256 + lane * 4);
    float4 q1 = *reinterpret_cast<const float4*>(g_q + (size_t)w * 256 + 128 + lane * 4);

    float qwe[8];
#pragma unroll
    for (int d = 0; d < 8; d++) {
        float p = dot4(q0, sWe4[d * 64 + lane]) + dot4(q1, sWe4[d * 64 + 32 + lane]);
#pragma unroll
        for (int o = 16; o; o >>= 1) p += __shfl_xor_sync(0xffffffffu, p, o);
        qwe[d] = p;
    }

    float m = -INFINITY, den = 0.f;
    float4 acc0 = make_float4(0, 0, 0, 0), acc1 = make_float4(0, 0, 0, 0);
    float4 pea0 = make_float4(0, 0, 0, 0), pea1 = make_float4(0, 0, 0, 0);
    int beg = g_offs[w], end = g_offs[w + 1];

    float4 k0, k1, v0, v1, e0, e1;
    if (beg < end) {
        int src = g_ssrc[beg], eid = g_seid[beg];
        const float4* kr = reinterpret_cast<const float4*>(g_k + (size_t)src * 256);
        const float4* vr = reinterpret_cast<const float4*>(g_v + (size_t)src * 256);
        const float4* ar = reinterpret_cast<const float4*>(edge_attr + (size_t)eid * 8);
        k0 = kr[lane]; k1 = kr[32 + lane];
        v0 = vr[lane]; v1 = vr[32 + lane];
        e0 = ar[0]; e1 = ar[1];
    }
    for (int t = beg; t < end; t++) {
        // prefetch next edge while computing current
        float4 nk0, nk1, nv0, nv1, ne0, ne1;
        bool more = (t + 1 < end);
        if (more) {
            int src = g_ssrc[t + 1], eid = g_seid[t + 1];
            const float4* kr = reinterpret_cast<const float4*>(g_k + (size_t)src * 256);
            const float4* vr = reinterpret_cast<const float4*>(g_v + (size_t)src * 256);
            const float4* ar = reinterpret_cast<const float4*>(edge_attr + (size_t)eid * 8);
            nk0 = kr[lane]; nk1 = kr[32 + lane];
            nv0 = vr[lane]; nv1 = vr[32 + lane];
            ne0 = ar[0]; ne1 = ar[1];
        }

        float dot = dot4(q0, k0) + dot4(q1, k1);
#pragma unroll
        for (int o = 16; o; o >>= 1) dot += __shfl_xor_sync(0xffffffffu, dot, o);
        float alpha = dot + qwe[0] * e0.x + qwe[1] * e0.y + qwe[2] * e0.z + qwe[3] * e0.w +
                      qwe[4] * e1.x + qwe[5] * e1.y + qwe[6] * e1.z + qwe[7] * e1.w;
        alpha *= 0.0625f;
        float mn = fmaxf(m, alpha);
        float corr = __expf(m - mn);
        float p = __expf(alpha - mn);
        m = mn;
        den = den * corr + p;
        acc0.x = acc0.x * corr + p * v0.x; acc0.y = acc0.y * corr + p * v0.y;
        acc0.z = acc0.z * corr + p * v0.z; acc0.w = acc0.w * corr + p * v0.w;
        acc1.x = acc1.x * corr + p * v1.x; acc1.y = acc1.y * corr + p * v1.y;
        acc1.z = acc1.z * corr + p * v1.z; acc1.w = acc1.w * corr + p * v1.w;
        pea0.x = pea0.x * corr + p * e0.x; pea0.y = pea0.y * corr + p * e0.y;
        pea0.z = pea0.z * corr + p * e0.z; pea0.w = pea0.w * corr + p * e0.w;
        pea1.x = pea1.x * corr + p * e1.x; pea1.y = pea1.y * corr + p * e1.y;
        pea1.z = pea1.z * corr + p * e1.z; pea1.w = pea1.w * corr + p * e1.w;

        if (more) { k0 = nk0; k1 = nk1; v0 = nv0; v1 = nv1; e0 = ne0; e1 = ne1; }
    }
    float inv = 1.f / (den + 1e-16f);
    float pe[8] = {pea0.x, pea0.y, pea0.z, pea0.w, pea1.x, pea1.y, pea1.z, pea1.w};
    float4 ex0 = make_float4(0, 0, 0, 0), ex1 = make_float4(0, 0, 0, 0);
#pragma unroll
    for (int d = 0; d < 8; d++) {
        float4 w0 = sWe4[d * 64 + lane], w1 = sWe4[d * 64 + 32 + lane];
        ex0.x += pe[d] * w0.x; ex0.y += pe[d] * w0.y; ex0.z += pe[d] * w0.z; ex0.w += pe[d] * w0.w;
        ex1.x += pe[d] * w1.x; ex1.y += pe[d] * w1.y; ex1.z += pe[d] * w1.z; ex1.w += pe[d] * w1.w;
    }
    float4 sk0 = *reinterpret_cast<const float4*>(g_sk + (size_t)w * 256 + lane * 4);
    float4 sk1 = *reinterpret_cast<const float4*>(g_sk + (size_t)w * 256 + 128 + lane * 4);
    float4 o0, o1;
    o0.x = fmaxf((acc0.x + ex0.x) * inv + sk0.x, 0.f);
    o0.y = fmaxf((acc0.y + ex0.y) * inv + sk0.y, 0.f);
    o0.z = fmaxf((acc0.z + ex0.z) * inv + sk0.z, 0.f);
    o0.w = fmaxf((acc0.w + ex0.w) * inv + sk0.w, 0.f);
    o1.x = fmaxf((acc1.x + ex1.x) * inv + sk1.x, 0.f);
    o1.y = fmaxf((acc1.y + ex1.y) * inv + sk1.y, 0.f);
    o1.z = fmaxf((acc1.z + ex1.z) * inv + sk1.z, 0.f);
    o1.w = fmaxf((acc1.w + ex1.w) * inv + sk1.w, 0.f);
    *reinterpret_cast<float4*>(hout + (size_t)w * 256 + lane * 4) = o0;
    *reinterpret_cast<float4*>(hout + (size_t)w * 256 + 128 + lane * 4) = o1;
    uint2 hi, lo;
    split4(o0, &hi, &lo);
    *reinterpret_cast<uint2*>(g_hb + (size_t)w * KTOT + lane * 4) = hi;
    *reinterpret_cast<uint2*>(g_hb + (size_t)w * KTOT + 256 + lane * 4) = lo;
    split4(o1, &hi, &lo);
    *reinterpret_cast<uint2*>(g_hb + (size_t)w * KTOT + 128 + lane * 4) = hi;
    *reinterpret_cast<uint2*>(g_hb + (size_t)w * KTOT + 256 + 128 + lane * 4) = lo;
}

// ---------------- decoder ----------------
__global__ void dec_kernel(const float* __restrict__ Wd, const float* __restrict__ bd,
                           float* __restrict__ out) {
    __shared__ float sW[18 * 256];
    __shared__ float sb[18];
    for (int i = threadIdx.x; i < 18 * 256; i += blockDim.x) {
        int j = i / 18, o = i % 18;
        sW[o * 256 + j] = Wd[i];
    }
    if (threadIdx.x < 18) sb[threadIdx.x] = bd[threadIdx.x];
    __syncthreads();
    int w = (blockIdx.x * blockDim.x + threadIdx.x) >> 5;
    int lane = threadIdx.x & 31;
    if (w >= N_NODES) return;
    const float* h = g_h[1];
    float hr[8];
#pragma unroll
    for (int i = 0; i < 8; i++) hr[i] = h[(size_t)w * 256 + lane + 32 * i];
    for (int o = 0; o < 18; o++) {
        float p = 0.f;
#pragma unroll
        for (int i = 0; i < 8; i++) p += hr[i] * sW[o * 256 + lane + 32 * i];
#pragma unroll
        for (int off = 16; off; off >>= 1) p += __shfl_xor_sync(0xffffffffu, p, off);
        if (lane == 0) out[w * 18 + o] = p + sb[o];
    }
}

// ---------------- launch ----------------
extern "C" void kernel_launch(void* const* d_in, const int* in_sizes, int n_in,
                              void* d_out, int out_size) {
    const float* x = (const float*)d_in[0];
    const int* ei = (const int*)d_in[1];
    const float* edge_attr = (const float*)d_in[2];
    const float* t = (const float*)d_in[3];
    const float* s = (const float*)d_in[4];
    const float* W_emb = (const float*)d_in[5];
    const float* b_emb = (const float*)d_in[6];
    const float* W_t = (const float*)d_in[7];
    const float* b_t = (const float*)d_in[8];
    const float* W_s = (const float*)d_in[9];
    const float* b_s = (const float*)d_in[10];
    const float* W_f = (const float*)d_in[11];
    const float* b_f = (const float*)d_in[12];
    const float* ln_g = (const float*)d_in[13];
    const float* ln_b = (const float*)d_in[14];
    const float* Wq = (const float*)d_in[15];
    const float* bq = (const float*)d_in[16];
    const float* Wk = (const float*)d_in[17];
    const float* bk = (const float*)d_in[18];
    const float* Wv = (const float*)d_in[19];
    const float* bv = (const float*)d_in[20];
    const float* We = (const float*)d_in[21];
    const float* be = (const float*)d_in[22];
    const float* Wskip = (const float*)d_in[23];
    const float* bskip = (const float*)d_in[24];
    const float* W_dec = (const float*)d_in[25];
    const float* b_dec = (const float*)d_in[26];
    float* out = (float*)d_out;
    (void)in_sizes; (void)n_in; (void)out_size;

    wconv_kernel<<<dim3(8, 8, 20), 256>>>(Wq, Wk, Wv, Wskip);                        // 0
    fuse_kernel<<<52, 256>>>(W_emb, W_t, W_s, W_f, b_emb, b_t, b_s, b_f, bskip, be); // 1
    encoder_kernel<<<296, 256>>>(x, t, s, ln_g, ln_b);                               // 2

    dim3 ggrid(157, 2, 4);
    gemm_wb<<<ggrid, 256>>>(0, bq, bk, bv);                                          // 3 <- profiled

    zero_deg_kernel<<<(N_NODES + 255) / 256, 256>>>();  // 4
    hist_kernel<<<(N_EDGES + 255) / 256, 256>>>(ei);    // 5
    scan_kernel<<<1, 1024>>>();                         // 6
    cursor_kernel<<<(N_NODES + 255) / 256, 256>>>();    // 7
    scatter_kernel<<<(N_EDGES + 255) / 256, 256>>>(ei); // 8

    int attn_blocks = (N_NODES * 32 + 255) / 256;
    attn_kernel<<<attn_blocks, 256>>>(We + 0 * 2048, edge_attr, 0);                  // 9
    for (int L = 1; L < N_LAYERS; L++) {
        int pin = L & 1;
        gemm_wb<<<ggrid, 256>>>(L, bq, bk, bv);
        attn_kernel<<<attn_blocks, 256>>>(We + L * 2048, edge_attr, pin);
    }
    dec_kernel<<<attn_blocks, 256>>>(W_dec, b_dec, out);
}

// round 9
// speedup vs baseline: 1.4561x; 1.4561x over previous
#include <cuda_runtime.h>
#include <cuda_bf16.h>
#include <math.h>
#include <stdint.h>
#include <mma.h>

using namespace nvcuda;

#define N_NODES 20000
#define N_EDGES 640000
#define HID 256
#define NH (N_NODES * HID)
#define N_LAYERS 5
#define KTOT 512       // stored split K (hi | lo)
#define GKCH 32        // GEMM K elements per pipelined chunk
#define GNCH 24        // 3 segments x 8 chunks: (hi,hi) (lo,hi) (hi,lo)
#define GLDA 40        // gemm smem leading dim (bf16; 80B, 16B-multiple)
#define LDS_STAGE 68   // epilogue staging ld (floats; 272B, 16B-multiple)

// ---------------- scratch ----------------
__device__ float g_h[2][NH];
__device__ float g_q[NH], g_k[NH], g_v[NH], g_sk[NH];
__device__ __align__(256) __nv_bfloat16 g_hb[N_NODES * KTOT];            // A split [M, hi|lo]
__device__ __align__(256) __nv_bfloat16 g_Wb[4 * N_LAYERS * 256 * KTOT]; // B split [N, hi|lo]
__device__ float g_M[46 * HID];
__device__ float g_bias[HID];
__device__ float g_skbias[N_LAYERS * HID];
__device__ int g_deg[N_NODES];
__device__ int g_offs[N_NODES + 1];
__device__ int g_cursor[N_NODES];
__device__ int g_ssrc[N_EDGES];
__device__ int g_seid[N_EDGES];

__device__ __forceinline__ void split_store(float v, __nv_bfloat16* hi_p, __nv_bfloat16* lo_p) {
    __nv_bfloat16 h = __float2bfloat16(v);
    *hi_p = h;
    *lo_p = __float2bfloat16(v - __bfloat162float(h));
}
__device__ __forceinline__ float dot4(float4 a, float4 b) {
    return a.x * b.x + a.y * b.y + a.z * b.z + a.w * b.w;
}
__device__ __forceinline__ void split4(float4 v, uint2* hi, uint2* lo) {
    __nv_bfloat16 hx = __float2bfloat16(v.x), hy = __float2bfloat16(v.y);
    __nv_bfloat16 hz = __float2bfloat16(v.z), hw = __float2bfloat16(v.w);
    __nv_bfloat162 h01 = __nv_bfloat162(hx, hy), h23 = __nv_bfloat162(hz, hw);
    hi->x = *reinterpret_cast<uint32_t*>(&h01);
    hi->y = *reinterpret_cast<uint32_t*>(&h23);
    __nv_bfloat162 l01 = __nv_bfloat162(__float2bfloat16(v.x - __bfloat162float(hx)),
                                        __float2bfloat16(v.y - __bfloat162float(hy)));
    __nv_bfloat162 l23 = __nv_bfloat162(__float2bfloat16(v.z - __bfloat162float(hz)),
                                        __float2bfloat16(v.w - __bfloat162float(hw)));
    lo->x = *reinterpret_cast<uint32_t*>(&l01);
    lo->y = *reinterpret_cast<uint32_t*>(&l23);
}
__device__ __forceinline__ void cp16(void* dst_smem, const void* src) {
    uint32_t d = (uint32_t)__cvta_generic_to_shared(dst_smem);
    asm volatile("cp.async.cg.shared.global [%0], [%1], 16;" :: "r"(d), "l"(src));
}
#define CP_COMMIT() asm volatile("cp.async.commit_group;" ::: "memory")
#define CP_WAIT1() asm volatile("cp.async.wait_group 1;" ::: "memory")
#define CP_WAIT0() asm volatile("cp.async.wait_group 0;" ::: "memory")

// ---------------- weight conversion: W[K,N] fp32 -> Wb[N, 512] bf16 (hi|lo) ----------------
__global__ void wconv_kernel(const float* __restrict__ Wq, const float* __restrict__ Wk,
                             const float* __restrict__ Wv, const float* __restrict__ Wsk) {
    __shared__ float s[32][33];
    int z = blockIdx.z;
    int w = z / N_LAYERS, l = z % N_LAYERS;
    const float* src = (w == 0) ? Wq : (w == 1) ? Wk : (w == 2) ? Wv : Wsk;
    src += l * 65536;
    __nv_bfloat16* dst = g_Wb + (size_t)z * 256 * KTOT;
    int k0 = blockIdx.x * 32, n0 = blockIdx.y * 32;
    int tx = threadIdx.x & 31, ty = threadIdx.x >> 5;
#pragma unroll
    for (int it = 0; it < 4; it++) {
        int r = ty + it * 8;
        s[r][tx] = src[(k0 + r) * 256 + n0 + tx];
    }
    __syncthreads();
#pragma unroll
    for (int it = 0; it < 4; it++) {
        int r = ty + it * 8;
        float v = s[tx][r];
        split_store(v, dst + (size_t)(n0 + r) * KTOT + k0 + tx,
                    dst + (size_t)(n0 + r) * KTOT + 256 + k0 + tx);
    }
}

// ---------------- fused encoder weights + skip-bias fold ----------------
__global__ void fuse_kernel(const float* __restrict__ W_emb, const float* __restrict__ W_t,
                            const float* __restrict__ W_s, const float* __restrict__ W_f,
                            const float* __restrict__ b_emb, const float* __restrict__ b_t,
                            const float* __restrict__ b_s, const float* __restrict__ b_f,
                            const float* __restrict__ bskip, const float* __restrict__ be) {
    int c = threadIdx.x;
    int r = blockIdx.x;
    if (r < 36) {
        float a = 0.f;
        for (int k = 0; k < 256; k++) a += W_emb[r * 256 + k] * W_f[k * 256 + c];
        g_M[r * 256 + c] = a;
    } else if (r < 40) {
        int rr = r - 36;
        float a = 0.f;
        for (int k = 0; k < 256; k++) a += W_t[rr * 256 + k] * W_f[(256 + k) * 256 + c];
        g_M[r * 256 + c] = a;
    } else if (r < 46) {
        int rr = r - 40;
        float a = 0.f;
        for (int k = 0; k < 256; k++) a += W_s[rr * 256 + k] * W_f[(512 + k) * 256 + c];
        g_M[r * 256 + c] = a;
    } else if (r == 46) {
        float a = b_f[c];
        for (int k = 0; k < 256; k++) {
            a += b_emb[k] * W_f[k * 256 + c];
            a += b_t[k] * W_f[(256 + k) * 256 + c];
            a += b_s[k] * W_f[(512 + k) * 256 + c];
        }
        g_bias[c] = a;
    } else {
        int l = r - 47;
        g_skbias[l * 256 + c] = bskip[l * 256 + c] + be[l * 256 + c];
    }
}

// ---------------- encoder ----------------
__global__ void encoder_kernel(const float* __restrict__ x, const float* __restrict__ t,
                               const float* __restrict__ s, const float* __restrict__ ln_g,
                               const float* __restrict__ ln_b) {
    __shared__ float sM[46 * 256];
    __shared__ float sb[256];
    __shared__ float sin_v[46];
    __shared__ float red[16];
    int tid = threadIdx.x;
    for (int i = tid; i < 46 * 256; i += 256) sM[i] = g_M[i];
    sb[tid] = g_bias[tid];
    float lg = ln_g[tid], lb = ln_b[tid];
    __syncthreads();
    for (int node = blockIdx.x; node < N_NODES; node += gridDim.x) {
        if (tid < 36) sin_v[tid] = x[node * 36 + tid];
        else if (tid < 40) sin_v[tid] = t[node * 4 + (tid - 36)];
        else if (tid < 46) sin_v[tid] = s[node * 6 + (tid - 40)];
        __syncthreads();
        float acc = sb[tid];
#pragma unroll
        for (int r = 0; r < 46; r++) acc += sin_v[r] * sM[r * 256 + tid];
        float ssum = acc, ssq = acc * acc;
#pragma unroll
        for (int o = 16; o; o >>= 1) {
            ssum += __shfl_xor_sync(0xffffffffu, ssum, o);
            ssq += __shfl_xor_sync(0xffffffffu, ssq, o);
        }
        if ((tid & 31) == 0) { red[tid >> 5] = ssum; red[8 + (tid >> 5)] = ssq; }
        __syncthreads();
        if (tid < 32) {
            float a = (tid < 8) ? red[tid] : 0.f;
            float b = (tid < 8) ? red[8 + tid] : 0.f;
#pragma unroll
            for (int o = 4; o; o >>= 1) {
                a += __shfl_xor_sync(0xffffffffu, a, o);
                b += __shfl_xor_sync(0xffffffffu, b, o);
            }
            if (tid == 0) { red[0] = a; red[1] = b; }
        }
        __syncthreads();
        float mu = red[0] * (1.f / 256.f);
        float var = red[1] * (1.f / 256.f) - mu * mu;
        float val = fmaxf((acc - mu) * rsqrtf(var + 1e-5f) * lg + lb, 0.f);
        g_h[0][node * 256 + tid] = val;
        split_store(val, g_hb + (size_t)node * KTOT + tid, g_hb + (size_t)node * KTOT + 256 + tid);
        __syncthreads();
    }
}

// ---------------- CSR build ----------------
__global__ void zero_deg_kernel() {
    int i = blockIdx.x * blockDim.x + threadIdx.x;
    if (i < N_NODES) g_deg[i] = 0;
}
__global__ void hist_kernel(const int* __restrict__ ei) {
    int e = blockIdx.x * blockDim.x + threadIdx.x;
    if (e < N_EDGES) atomicAdd(&g_deg[ei[N_EDGES + e]], 1);
}
__global__ void scan_kernel() {
    __shared__ int sh[1024];
    __shared__ int carry;
    int tid = threadIdx.x;
    if (tid == 0) carry = 0;
    __syncthreads();
    for (int base = 0; base < N_NODES; base += 1024) {
        int i = base + tid;
        int v = (i < N_NODES) ? g_deg[i] : 0;
        sh[tid] = v;
        __syncthreads();
        for (int off = 1; off < 1024; off <<= 1) {
            int tadd = (tid >= off) ? sh[tid - off] : 0;
            __syncthreads();
            sh[tid] += tadd;
            __syncthreads();
        }
        int incl = sh[tid];
        if (i < N_NODES) g_offs[i] = carry + incl - v;
        __syncthreads();
        if (tid == 1023) carry += sh[1023];
        __syncthreads();
    }
    if (tid == 0) g_offs[N_NODES] = carry;
}
__global__ void cursor_kernel() {
    int i = blockIdx.x * blockDim.x + threadIdx.x;
    if (i < N_NODES) g_cursor[i] = g_offs[i];
}
__global__ void scatter_kernel(const int* __restrict__ ei) {
    int e = blockIdx.x * blockDim.x + threadIdx.x;
    if (e < N_EDGES) {
        int d = ei[N_EDGES + e];
        int pos = atomicAdd(&g_cursor[d], 1);
        g_ssrc[pos] = ei[e];
        g_seid[pos] = e;
    }
}

// ---------------- bf16 wmma GEMM, 128x128 tile, cp.async double-buffered ----------------
__global__ void __launch_bounds__(256)
gemm_wb(int layer, const float* __restrict__ bq_, const float* __restrict__ bk_,
        const float* __restrict__ bv_) {
    __shared__ __align__(16) __nv_bfloat16 smem_all[2 * 2 * 128 * GLDA];
    __shared__ float sbias[128];

    int tid = threadIdx.x;
    int wid = tid >> 5, lane = tid & 31;
    int wr = wid >> 1, wc = wid & 1;
    int w = blockIdx.z;
    int row0 = blockIdx.x * 128;
    int colblk = blockIdx.y * 128;
    int col0 = colblk + wc * 64;

    const __nv_bfloat16* Bsrc = g_Wb + ((size_t)w * N_LAYERS + layer) * 256 * KTOT;
    float* C;
    const float* bias;
    if (w == 0) { C = g_q; bias = bq_ + layer * 256; }
    else if (w == 1) { C = g_k; bias = bk_ + layer * 256; }
    else if (w == 2) { C = g_v; bias = bv_ + layer * 256; }
    else { C = g_sk; bias = g_skbias + layer * 256; }

    if (tid < 128) sbias[tid] = bias[colblk + tid];

    int l0 = tid, l1 = tid + 256;
    int ar0 = l0 >> 2, ak0 = (l0 & 3) * 8;
    int ar1 = l1 >> 2, ak1 = (l1 & 3) * 8;
    int gr0 = row0 + ar0; if (gr0 >= N_NODES) gr0 = N_NODES - 1;
    int gr1 = row0 + ar1; if (gr1 >= N_NODES) gr1 = N_NODES - 1;

    wmma::fragment<wmma::accumulator, 16, 16, 16, float> acc[2][4];
#pragma unroll
    for (int m = 0; m < 2; m++)
#pragma unroll
        for (int n = 0; n < 4; n++) wmma::fill_fragment(acc[m][n], 0.f);

    auto issue = [&](int c, int buf) {
        int seg = c >> 3, cc = c & 7;
        int aoff = (seg == 1) ? 256 : 0;
        int boff = (seg == 2) ? 256 : 0;
        __nv_bfloat16* As = smem_all + buf * 2 * 128 * GLDA;
        __nv_bfloat16* Bs = As + 128 * GLDA;
        cp16(As + ar0 * GLDA + ak0, g_hb + (size_t)gr0 * KTOT + aoff + cc * GKCH + ak0);
        cp16(As + ar1 * GLDA + ak1, g_hb + (size_t)gr1 * KTOT + aoff + cc * GKCH + ak1);
        cp16(Bs + ar0 * GLDA + ak0, Bsrc + (size_t)(colblk + ar0) * KTOT + boff + cc * GKCH + ak0);
        cp16(Bs + ar1 * GLDA + ak1, Bsrc + (size_t)(colblk + ar1) * KTOT + boff + cc * GKCH + ak1);
        CP_COMMIT();
    };

    issue(0, 0);
    for (int c = 0; c < GNCH; c++) {
        if (c + 1 < GNCH) { issue(c + 1, (c + 1) & 1); CP_WAIT1(); }
        else { CP_WAIT0(); }
        __syncthreads();
        __nv_bfloat16* As = smem_all + (c & 1) * 2 * 128 * GLDA;
        __nv_bfloat16* Bs = As + 128 * GLDA;
#pragma unroll
        for (int ks = 0; ks < 2; ks++) {
            wmma::fragment<wmma::matrix_a, 16, 16, 16, __nv_bfloat16, wmma::row_major> af[2];
            wmma::fragment<wmma::matrix_b, 16, 16, 16, __nv_bfloat16, wmma::col_major> bf[4];
#pragma unroll
            for (int m = 0; m < 2; m++)
                wmma::load_matrix_sync(af[m], As + (wr * 32 + m * 16) * GLDA + ks * 16, GLDA);
#pragma unroll
            for (int n = 0; n < 4; n++)
                wmma::load_matrix_sync(bf[n], Bs + (wc * 64 + n * 16) * GLDA + ks * 16, GLDA);
#pragma unroll
            for (int m = 0; m < 2; m++)
#pragma unroll
                for (int n = 0; n < 4; n++) wmma::mma_sync(acc[m][n], af[m], bf[n], acc[m][n]);
        }
        __syncthreads();
    }

    float* stage = reinterpret_cast<float*>(smem_all) + wid * 16 * LDS_STAGE;
#pragma unroll
    for (int m = 0; m < 2; m++) {
        __syncwarp();
#pragma unroll
        for (int n = 0; n < 4; n++)
            wmma::store_matrix_sync(stage + n * 16, acc[m][n], LDS_STAGE, wmma::mem_row_major);
        __syncwarp();
        int rbase = row0 + wr * 32 + m * 16;
#pragma unroll
        for (int i = lane; i < 16 * 64; i += 32) {
            int r = i >> 6, cc2 = i & 63;
            int gr = rbase + r;
            if (gr < N_NODES)
                C[(size_t)gr * 256 + col0 + cc2] = stage[r * LDS_STAGE + cc2] + sbias[wc * 64 + cc2];
        }
        __syncwarp();
    }
}

// ---------------- attention: float4 lane layout (R7 version, no prefetch) ----------------
__global__ void attn_kernel(const float* __restrict__ We_l, const float* __restrict__ edge_attr,
                            int pin) {
    __shared__ float sWe[8 * 256];
    for (int i = threadIdx.x; i < 2048; i += blockDim.x) sWe[i] = We_l[i];
    __syncthreads();
    const float4* sWe4 = reinterpret_cast<const float4*>(sWe);
    int w = (blockIdx.x * blockDim.x + threadIdx.x) >> 5;
    int lane = threadIdx.x & 31;
    if (w >= N_NODES) return;
    float* hout = g_h[pin ^ 1];

    float4 q0 = *reinterpret_cast<const float4*>(g_q + (size_t)w * 256 + lane * 4);
    float4 q1 = *reinterpret_cast<const float4*>(g_q + (size_t)w * 256 + 128 + lane * 4);

    float qwe[8];
#pragma unroll
    for (int d = 0; d < 8; d++) {
        float p = dot4(q0, sWe4[d * 64 + lane]) + dot4(q1, sWe4[d * 64 + 32 + lane]);
#pragma unroll
        for (int o = 16; o; o >>= 1) p += __shfl_xor_sync(0xffffffffu, p, o);
        qwe[d] = p;
    }

    float m = -INFINITY, den = 0.f;
    float4 acc0 = make_float4(0, 0, 0, 0), acc1 = make_float4(0, 0, 0, 0);
    float4 pea0 = make_float4(0, 0, 0, 0), pea1 = make_float4(0, 0, 0, 0);
    int beg = g_offs[w], end = g_offs[w + 1];
    for (int t = beg; t < end; t++) {
        int src = g_ssrc[t];
        int eid = g_seid[t];
        const float4* kr = reinterpret_cast<const float4*>(g_k + (size_t)src * 256);
        const float4* vr = reinterpret_cast<const float4*>(g_v + (size_t)src * 256);
        const float4* ar = reinterpret_cast<const float4*>(edge_attr + (size_t)eid * 8);
        float4 k0 = kr[lane], k1 = kr[32 + lane];
        float4 v0 = vr[lane], v1 = vr[32 + lane];
        float4 e0 = ar[0], e1 = ar[1];

        float dot = dot4(q0, k0) + dot4(q1, k1);
#pragma unroll
        for (int o = 16; o; o >>= 1) dot += __shfl_xor_sync(0xffffffffu, dot, o);
        float alpha = dot + qwe[0] * e0.x + qwe[1] * e0.y + qwe[2] * e0.z + qwe[3] * e0.w +
                      qwe[4] * e1.x + qwe[5] * e1.y + qwe[6] * e1.z + qwe[7] * e1.w;
        alpha *= 0.0625f;
        float mn = fmaxf(m, alpha);
        float corr = __expf(m - mn);
        float p = __expf(alpha - mn);
        m = mn;
        den = den * corr + p;
        acc0.x = acc0.x * corr + p * v0.x; acc0.y = acc0.y * corr + p * v0.y;
        acc0.z = acc0.z * corr + p * v0.z; acc0.w = acc0.w * corr + p * v0.w;
        acc1.x = acc1.x * corr + p * v1.x; acc1.y = acc1.y * corr + p * v1.y;
        acc1.z = acc1.z * corr + p * v1.z; acc1.w = acc1.w * corr + p * v1.w;
        pea0.x = pea0.x * corr + p * e0.x; pea0.y = pea0.y * corr + p * e0.y;
        pea0.z = pea0.z * corr + p * e0.z; pea0.w = pea0.w * corr + p * e0.w;
        pea1.x = pea1.x * corr + p * e1.x; pea1.y = pea1.y * corr + p * e1.y;
        pea1.z = pea1.z * corr + p * e1.z; pea1.w = pea1.w * corr + p * e1.w;
    }
    float inv = 1.f / (den + 1e-16f);
    float pe[8] = {pea0.x, pea0.y, pea0.z, pea0.w, pea1.x, pea1.y, pea1.z, pea1.w};
    float4 ex0 = make_float4(0, 0, 0, 0), ex1 = make_float4(0, 0, 0, 0);
#pragma unroll
    for (int d = 0; d < 8; d++) {
        float4 w0 = sWe4[d * 64 + lane], w1 = sWe4[d * 64 + 32 + lane];
        ex0.x += pe[d] * w0.x; ex0.y += pe[d] * w0.y; ex0.z += pe[d] * w0.z; ex0.w += pe[d] * w0.w;
        ex1.x += pe[d] * w1.x; ex1.y += pe[d] * w1.y; ex1.z += pe[d] * w1.z; ex1.w += pe[d] * w1.w;
    }
    float4 sk0 = *reinterpret_cast<const float4*>(g_sk + (size_t)w * 256 + lane * 4);
    float4 sk1 = *reinterpret_cast<const float4*>(g_sk + (size_t)w * 256 + 128 + lane * 4);
    float4 o0, o1;
    o0.x = fmaxf((acc0.x + ex0.x) * inv + sk0.x, 0.f);
    o0.y = fmaxf((acc0.y + ex0.y) * inv + sk0.y, 0.f);
    o0.z = fmaxf((acc0.z + ex0.z) * inv + sk0.z, 0.f);
    o0.w = fmaxf((acc0.w + ex0.w) * inv + sk0.w, 0.f);
    o1.x = fmaxf((acc1.x + ex1.x) * inv + sk1.x, 0.f);
    o1.y = fmaxf((acc1.y + ex1.y) * inv + sk1.y, 0.f);
    o1.z = fmaxf((acc1.z + ex1.z) * inv + sk1.z, 0.f);
    o1.w = fmaxf((acc1.w + ex1.w) * inv + sk1.w, 0.f);
    *reinterpret_cast<float4*>(hout + (size_t)w * 256 + lane * 4) = o0;
    *reinterpret_cast<float4*>(hout + (size_t)w * 256 + 128 + lane * 4) = o1;
    uint2 hi, lo;
    split4(o0, &hi, &lo);
    *reinterpret_cast<uint2*>(g_hb + (size_t)w * KTOT + lane * 4) = hi;
    *reinterpret_cast<uint2*>(g_hb + (size_t)w * KTOT + 256 + lane * 4) = lo;
    split4(o1, &hi, &lo);
    *reinterpret_cast<uint2*>(g_hb + (size_t)w * KTOT + 128 + lane * 4) = hi;
    *reinterpret_cast<uint2*>(g_hb + (size_t)w * KTOT + 256 + 128 + lane * 4) = lo;
}

// ---------------- decoder ----------------
__global__ void dec_kernel(const float* __restrict__ Wd, const float* __restrict__ bd,
                           float* __restrict__ out) {
    __shared__ float sW[18 * 256];
    __shared__ float sb[18];
    for (int i = threadIdx.x; i < 18 * 256; i += blockDim.x) {
        int j = i / 18, o = i % 18;
        sW[o * 256 + j] = Wd[i];
    }
    if (threadIdx.x < 18) sb[threadIdx.x] = bd[threadIdx.x];
    __syncthreads();
    int w = (blockIdx.x * blockDim.x + threadIdx.x) >> 5;
    int lane = threadIdx.x & 31;
    if (w >= N_NODES) return;
    const float* h = g_h[1];
    float hr[8];
#pragma unroll
    for (int i = 0; i < 8; i++) hr[i] = h[(size_t)w * 256 + lane + 32 * i];
    for (int o = 0; o < 18; o++) {
        float p = 0.f;
#pragma unroll
        for (int i = 0; i < 8; i++) p += hr[i] * sW[o * 256 + lane + 32 * i];
#pragma unroll
        for (int off = 16; off; off >>= 1) p += __shfl_xor_sync(0xffffffffu, p, off);
        if (lane == 0) out[w * 18 + o] = p + sb[o];
    }
}

// ---------------- launch ----------------
extern "C" void kernel_launch(void* const* d_in, const int* in_sizes, int n_in,
                              void* d_out, int out_size) {
    const float* x = (const float*)d_in[0];
    const int* ei = (const int*)d_in[1];
    const float* edge_attr = (const float*)d_in[2];
    const float* t = (const float*)d_in[3];
    const float* s = (const float*)d_in[4];
    const float* W_emb = (const float*)d_in[5];
    const float* b_emb = (const float*)d_in[6];
    const float* W_t = (const float*)d_in[7];
    const float* b_t = (const float*)d_in[8];
    const float* W_s = (const float*)d_in[9];
    const float* b_s = (const float*)d_in[10];
    const float* W_f = (const float*)d_in[11];
    const float* b_f = (const float*)d_in[12];
    const float* ln_g = (const float*)d_in[13];
    const float* ln_b = (const float*)d_in[14];
    const float* Wq = (const float*)d_in[15];
    const float* bq = (const float*)d_in[16];
    const float* Wk = (const float*)d_in[17];
    const float* bk = (const float*)d_in[18];
    const float* Wv = (const float*)d_in[19];
    const float* bv = (const float*)d_in[20];
    const float* We = (const float*)d_in[21];
    const float* be = (const float*)d_in[22];
    const float* Wskip = (const float*)d_in[23];
    const float* bskip = (const float*)d_in[24];
    const float* W_dec = (const float*)d_in[25];
    const float* b_dec = (const float*)d_in[26];
    float* out = (float*)d_out;
    (void)in_sizes; (void)n_in; (void)out_size;

    wconv_kernel<<<dim3(8, 8, 20), 256>>>(Wq, Wk, Wv, Wskip);                        // 0
    fuse_kernel<<<52, 256>>>(W_emb, W_t, W_s, W_f, b_emb, b_t, b_s, b_f, bskip, be); // 1
    encoder_kernel<<<296, 256>>>(x, t, s, ln_g, ln_b);                               // 2

    dim3 ggrid(157, 2, 4);
    gemm_wb<<<ggrid, 256>>>(0, bq, bk, bv);                                          // 3 <- profiled

    zero_deg_kernel<<<(N_NODES + 255) / 256, 256>>>();  // 4
    hist_kernel<<<(N_EDGES + 255) / 256, 256>>>(ei);    // 5
    scan_kernel<<<1, 1024>>>();                         // 6
    cursor_kernel<<<(N_NODES + 255) / 256, 256>>>();    // 7
    scatter_kernel<<<(N_EDGES + 255) / 256, 256>>>(ei); // 8

    int attn_blocks = (N_NODES * 32 + 255) / 256;
    attn_kernel<<<attn_blocks, 256>>>(We + 0 * 2048, edge_attr, 0);                  // 9
    for (int L = 1; L < N_LAYERS; L++) {
        int pin = L & 1;
        gemm_wb<<<ggrid, 256>>>(L, bq, bk, bv);
        attn_kernel<<<attn_blocks, 256>>>(We + L * 2048, edge_attr, pin);
    }
    dec_kernel<<<attn_blocks, 256>>>(W_dec, b_dec, out);
}